// round 7
// baseline (speedup 1.0000x reference)
#include <cuda_runtime.h>

// SpatialLoss on GB300 (sm_103a)
//
// Math reduction: conv is linear, so
//   d = grad_conv(avgpool4(mean_c(x))) - grad_conv(avgpool4(mean_c(pred)))
//     = grad_conv(avgpool4(mean_c(x - pred)))
// loss = mean over (B,128,128) of (dl^2 + dr^2 + du^2 + dd^2)
// with dl = p[i,j]-p[i,j-1] (0 outside), dr = p[i,j]-p[i,j+1], etc.
//
// Pass 1 (HBM-bound, ~201 MB read): pooled channel-mean diff -> g_pool (2 MB)
// Pass 2 (L2-resident): neighbor diffs, square-sum, block reduce, atomicAdd.

#define BB 32
#define CC 3
#define HH 512
#define WW 512
#define PH 128
#define PW 128
#define NPIX (BB * PH * PW)   // 524288

__device__ float g_pool[NPIX];

__global__ void __launch_bounds__(256) pool_diff_kernel(
    const float* __restrict__ x, const float* __restrict__ pred)
{
    const int idx = blockIdx.x * blockDim.x + threadIdx.x;  // exactly NPIX threads
    const int j = idx & (PW - 1);
    const int i = (idx >> 7) & (PH - 1);
    const int b = idx >> 14;

    const float4* __restrict__ x4 = (const float4*)x;
    const float4* __restrict__ p4 = (const float4*)pred;

    float s = 0.0f;
#pragma unroll
    for (int c = 0; c < CC; c++) {
#pragma unroll
        for (int dh = 0; dh < 4; dh++) {
            const int off = ((b * CC + c) * HH + (4 * i + dh)) * (WW / 4) + j;
            const float4 a = x4[off];
            const float4 q = p4[off];
            s += (a.x - q.x) + (a.y - q.y) + (a.z - q.z) + (a.w - q.w);
        }
    }
    g_pool[idx] = s * (1.0f / 48.0f);
}

__global__ void __launch_bounds__(256) grad_loss_kernel(float* __restrict__ out)
{
    const int idx = blockIdx.x * blockDim.x + threadIdx.x;  // exactly NPIX threads
    const int j = idx & (PW - 1);
    const int i = (idx >> 7) & (PH - 1);
    const int b = idx >> 14;

    const float* __restrict__ p = g_pool + b * PH * PW;
    const int rc = i * PW + j;

    const float c = p[rc];
    const float l = (j > 0)      ? p[rc - 1]  : 0.0f;
    const float r = (j < PW - 1) ? p[rc + 1]  : 0.0f;
    const float u = (i > 0)      ? p[rc - PW] : 0.0f;
    const float d = (i < PH - 1) ? p[rc + PW] : 0.0f;

    const float dl = c - l, dr = c - r, du = c - u, dd = c - d;
    float acc = dl * dl + dr * dr + du * du + dd * dd;

    // warp reduction
#pragma unroll
    for (int off = 16; off > 0; off >>= 1)
        acc += __shfl_down_sync(0xFFFFFFFFu, acc, off);

    __shared__ float warp_sums[8];
    const int lane = threadIdx.x & 31;
    const int wid  = threadIdx.x >> 5;
    if (lane == 0) warp_sums[wid] = acc;
    __syncthreads();

    if (wid == 0) {
        float v = (lane < 8) ? warp_sums[lane] : 0.0f;
#pragma unroll
        for (int off = 4; off > 0; off >>= 1)
            v += __shfl_down_sync(0xFFFFFFFFu, v, off);
        if (lane == 0)
            atomicAdd(out, v * (1.0f / (float)NPIX));
    }
}

extern "C" void kernel_launch(void* const* d_in, const int* in_sizes, int n_in,
                              void* d_out, int out_size)
{
    const float* x    = (const float*)d_in[0];
    const float* pred = (const float*)d_in[1];
    float* out = (float*)d_out;

    // d_out is poisoned; zero it (memset node is graph-capturable)
    cudaMemsetAsync(out, 0, sizeof(float));

    const int threads = 256;
    const int blocks  = NPIX / threads;  // 2048, exact

    pool_diff_kernel<<<blocks, threads>>>(x, pred);
    grad_loss_kernel<<<blocks, threads>>>(out);
}

// round 10
// speedup vs baseline: 1.0430x; 1.0430x over previous
#include <cuda_runtime.h>

// SpatialLoss on GB300 (sm_103a)
//
// Math reduction: conv is linear, so
//   d = grad_conv(avgpool4(mean_c(x))) - grad_conv(avgpool4(mean_c(pred)))
//     = grad_conv(avgpool4(mean_c(x - pred)))
// loss = mean over (B,128,128) of (dl^2 + dr^2 + du^2 + dd^2)
//
// Pass 1 (HBM-bound, 201 MB streamed, __ldcs evict-first): pooled
//   channel-mean diff -> g_pool (2 MB, L2-resident).
// Pass 2 (L2-resident stencil): float4 stencil, 4 px/vec, 4 vec/thread,
//   128 blocks -> 128 same-address atomics (was 2048 @ 1px/thread).

#define BB 32
#define CC 3
#define HH 512
#define WW 512
#define PH 128
#define PW 128
#define NPIX (BB * PH * PW)      // 524288
#define NVEC (NPIX / 4)          // 131072 float4 positions
#define ROWV (PW / 4)            // 32 float4 per pooled row

__device__ float g_pool[NPIX];

__global__ void __launch_bounds__(256) pool_diff_kernel(
    const float* __restrict__ x, const float* __restrict__ pred)
{
    const int idx = blockIdx.x * blockDim.x + threadIdx.x;  // exactly NPIX threads
    const int j = idx & (PW - 1);
    const int i = (idx >> 7) & (PH - 1);
    const int b = idx >> 14;

    const float4* __restrict__ x4 = (const float4*)x;
    const float4* __restrict__ p4 = (const float4*)pred;

    float s = 0.0f;
#pragma unroll
    for (int c = 0; c < CC; c++) {
#pragma unroll
        for (int dh = 0; dh < 4; dh++) {
            const int off = ((b * CC + c) * HH + (4 * i + dh)) * (WW / 4) + j;
            const float4 a = __ldcs(&x4[off]);   // streaming: no reuse, evict-first
            const float4 q = __ldcs(&p4[off]);
            s += (a.x - q.x) + (a.y - q.y) + (a.z - q.z) + (a.w - q.w);
        }
    }
    g_pool[idx] = s * (1.0f / 48.0f);
}

// 128 blocks x 256 threads, 4 float4-items per thread (grid-strided).
__global__ void __launch_bounds__(256) grad_loss_kernel(float* __restrict__ out)
{
    const float4* __restrict__ p4 = (const float4*)g_pool;
    const int nthreads = gridDim.x * blockDim.x;           // 32768
    int v = blockIdx.x * blockDim.x + threadIdx.x;

    float acc = 0.0f;
#pragma unroll
    for (int it = 0; it < 4; it++, v += nthreads) {
        const int j4 = v & (ROWV - 1);
        const int i  = (v >> 5) & (PH - 1);

        const float4 c = p4[v];
        const float4 u = (i > 0)      ? p4[v - ROWV] : make_float4(0.f, 0.f, 0.f, 0.f);
        const float4 d = (i < PH - 1) ? p4[v + ROWV] : make_float4(0.f, 0.f, 0.f, 0.f);
        const float* p = g_pool;
        const float lm = (j4 > 0)        ? p[v * 4 - 1] : 0.0f;  // left halo of px0
        const float rp = (j4 < ROWV - 1) ? p[v * 4 + 4] : 0.0f;  // right halo of px3

        // px0
        {
            const float dl = c.x - lm,  dr = c.x - c.y, du = c.x - u.x, dd = c.x - d.x;
            acc += dl * dl + dr * dr + du * du + dd * dd;
        }
        // px1
        {
            const float dl = c.y - c.x, dr = c.y - c.z, du = c.y - u.y, dd = c.y - d.y;
            acc += dl * dl + dr * dr + du * du + dd * dd;
        }
        // px2
        {
            const float dl = c.z - c.y, dr = c.z - c.w, du = c.z - u.z, dd = c.z - d.z;
            acc += dl * dl + dr * dr + du * du + dd * dd;
        }
        // px3
        {
            const float dl = c.w - c.z, dr = c.w - rp,  du = c.w - u.w, dd = c.w - d.w;
            acc += dl * dl + dr * dr + du * du + dd * dd;
        }
    }

    // warp reduction
#pragma unroll
    for (int off = 16; off > 0; off >>= 1)
        acc += __shfl_down_sync(0xFFFFFFFFu, acc, off);

    __shared__ float warp_sums[8];
    const int lane = threadIdx.x & 31;
    const int wid  = threadIdx.x >> 5;
    if (lane == 0) warp_sums[wid] = acc;
    __syncthreads();

    if (wid == 0) {
        float s = (lane < 8) ? warp_sums[lane] : 0.0f;
#pragma unroll
        for (int off = 4; off > 0; off >>= 1)
            s += __shfl_down_sync(0xFFFFFFFFu, s, off);
        if (lane == 0)
            atomicAdd(out, s * (1.0f / (float)NPIX));
    }
}

extern "C" void kernel_launch(void* const* d_in, const int* in_sizes, int n_in,
                              void* d_out, int out_size)
{
    const float* x    = (const float*)d_in[0];
    const float* pred = (const float*)d_in[1];
    float* out = (float*)d_out;

    cudaMemsetAsync(out, 0, sizeof(float));

    pool_diff_kernel<<<NPIX / 256, 256>>>(x, pred);
    grad_loss_kernel<<<NVEC / (256 * 4), 256>>>(out);   // 128 blocks
}